// round 8
// baseline (speedup 1.0000x reference)
#include <cuda_runtime.h>
#include <cuda_bf16.h>

// Problem shape (fixed by the dataset)
#define Bv 8
#define Cv 256
#define Lv 4096
#define Kv 8
#define Gv 4              // channels per CTA (share exp/weight computation)
#define TPB 1024
#define NJ (Lv / 4)       // float4s per row = 1024 ( == TPB -> ITERS = 1 )

#define SMEM_BYTES (2 * Gv * Lv * 4)   // sat + sap = 131072 B

// ---------------------------------------------------------------------------
// Math: softmax identity  w_k(l) = E[l-k] / sum_k' E[l-k'],  E = exp(dt)
// (the exp(-dt[l]) base cancels). Additionally, the at-numerators for the 4
// elements of one float4 are windowed sums of the SAME products
// p[m] = E[m]*x[m]:  num_c = sum_{m=c+1}^{c+8} p[m]  -> 11 MUL + 16 ADD
// instead of 32 FMA. at[l<7] = 0 exactly (reference's BIG sentinel).
// ---------------------------------------------------------------------------
__global__ void __launch_bounds__(TPB, 1) fused_kernel(
    const float* __restrict__ x,
    const float* __restrict__ dt,
    const float* __restrict__ kt,
    float* __restrict__ out)
{
    extern __shared__ float smem[];
    float4* sat = (float4*)smem;               // [Gv][NJ]
    float4* sap = (float4*)(smem + Gv * Lv);   // [Gv][NJ]
    __shared__ float sred[32][Gv * 3];
    __shared__ float scoef[Gv][2];

    const int b   = blockIdx.x >> 6;           // / (Cv/Gv = 64)
    const int c0  = (blockIdx.x & 63) * Gv;
    const int j   = threadIdx.x;               // float4 index within row
    const int lid = j & 31;
    const int wid = j >> 5;

    const float4* dtr = (const float4*)(dt + (size_t)b * Lv);
    const float4 zero4 = make_float4(0.f, 0.f, 0.f, 0.f);

    float ktr[Kv];
#pragma unroll
    for (int k = 0; k < Kv; k++) ktr[k] = __ldg(&kt[k]);

    // ---- dt window [4j-8 .. 4j+3] -> E = exp(dt) ----
    float Ew[12];
    {
        float4 m2 = (j >= 2) ? dtr[j - 2] : zero4;
        float4 m1 = (j >= 1) ? dtr[j - 1] : zero4;
        float4 d0 = dtr[j];
        Ew[0] = m2.x; Ew[1] = m2.y; Ew[2]  = m2.z; Ew[3]  = m2.w;
        Ew[4] = m1.x; Ew[5] = m1.y; Ew[6]  = m1.z; Ew[7]  = m1.w;
        Ew[8] = d0.x; Ew[9] = d0.y; Ew[10] = d0.z; Ew[11] = d0.w;
#pragma unroll
        for (int m = 0; m < 12; m++) Ew[m] = __expf(Ew[m]);
    }

    // ---- reciprocal 8-tap sums (shared factored partials) ----
    float inv[4];
    {
        float c45  = Ew[4] + Ew[5];
        float c67  = Ew[6] + Ew[7];
        float core = (c45 + c67) + Ew[8];          // E[4..8]
        float s23  = Ew[2] + Ew[3];
        float s910 = Ew[9] + Ew[10];
        inv[0] = __fdividef(1.0f, core + (Ew[1] + s23));    // E[1..8]
        inv[1] = __fdividef(1.0f, core + (s23 + Ew[9]));    // E[2..9]
        inv[2] = __fdividef(1.0f, core + (Ew[3] + s910));   // E[3..10]
        inv[3] = __fdividef(1.0f, core + (s910 + Ew[11]));  // E[4..11]
    }

    float gr[Gv * 3];
#pragma unroll
    for (int q = 0; q < Gv * 3; q++) gr[q] = 0.f;

#pragma unroll
    for (int g = 0; g < Gv; g++) {
        const float4* xr = (const float4*)(x + (size_t)(b * Cv + c0 + g) * Lv);
        float4 xm2 = (j >= 2) ? xr[j - 2] : zero4;
        float4 xm1 = (j >= 1) ? xr[j - 1] : zero4;
        float4 x0  = xr[j];
        float xw[12] = {xm2.x, xm2.y, xm2.z, xm2.w,
                        xm1.x, xm1.y, xm1.z, xm1.w,
                        x0.x,  x0.y,  x0.z,  x0.w};

        // products p[m] = E[m]*x[m], m = 1..11
        float p[12];
#pragma unroll
        for (int m = 1; m < 12; m++) p[m] = Ew[m] * xw[m];

        // windowed numerators (shared core p[4..8])
        float c45  = p[4] + p[5];
        float c67  = p[6] + p[7];
        float core = (c45 + c67) + p[8];
        float s23  = p[2] + p[3];
        float s910 = p[9] + p[10];
        float num[4];
        num[0] = core + (p[1] + s23);
        num[1] = core + (s23 + p[9]);
        num[2] = core + (p[3] + s910);
        num[3] = core + (s910 + p[11]);

        float4 atv, apv;
        float* atf = (float*)&atv;
        float* apf = (float*)&apv;
#pragma unroll
        for (int c = 0; c < 4; c++) {
            float a_p = 0.f;
#pragma unroll
            for (int k = 0; k < Kv; k++)
                a_p = fmaf(ktr[k], xw[8 + c - k], a_p);
            float a_t = num[c] * inv[c];
            if (4 * j + c < Kv - 1) a_t = 0.f;   // BIG-sentinel mask (j<2 only)
            atf[c] = a_t;
            apf[c] = a_p;
            gr[g * 3 + 0] = fmaf(a_t, a_t, gr[g * 3 + 0]);
            gr[g * 3 + 1] = fmaf(a_t, a_p, gr[g * 3 + 1]);
            gr[g * 3 + 2] = fmaf(a_p, a_p, gr[g * 3 + 2]);
        }
        sat[g * NJ + j] = atv;
        sap[g * NJ + j] = apv;
    }

    // ---- block reduction of 12 Gram scalars (32 warps) ----
#pragma unroll
    for (int q = 0; q < Gv * 3; q++) {
        float v = gr[q];
#pragma unroll
        for (int o = 16; o > 0; o >>= 1)
            v += __shfl_xor_sync(0xffffffffu, v, o);
        if (lid == 0) sred[wid][q] = v;
    }
    __syncthreads();
    if (j < Gv) {
        float G00 = 0.f, G01 = 0.f, G11 = 0.f;
#pragma unroll
        for (int wq = 0; wq < 32; wq++) {
            G00 += sred[wq][j * 3 + 0];
            G01 += sred[wq][j * 3 + 1];
            G11 += sred[wq][j * 3 + 2];
        }
        // scores row0 = softmax([G00,G01]); row1 = softmax([G01,G11])
        // out = 0.5*((s00+s10)*at + ((1-s00)+(1-s10))*ap)
        float s00 = 1.0f / (1.0f + __expf(G01 - G00));
        float s10 = 1.0f / (1.0f + __expf(G11 - G01));
        scoef[j][0] = 0.5f * (s00 + s10);
        scoef[j][1] = 0.5f * ((1.0f - s00) + (1.0f - s10));
    }
    __syncthreads();

    // ---- pass 2: out = ca*at + cb*ap (LDS.128 -> STG.128) ----
#pragma unroll
    for (int g = 0; g < Gv; g++) {
        const float ca = scoef[g][0];
        const float cb = scoef[g][1];
        float4 a = sat[g * NJ + j];
        float4 p2 = sap[g * NJ + j];
        float4 o;
        o.x = fmaf(ca, a.x, cb * p2.x);
        o.y = fmaf(ca, a.y, cb * p2.y);
        o.z = fmaf(ca, a.z, cb * p2.z);
        o.w = fmaf(ca, a.w, cb * p2.w);
        ((float4*)(out + (size_t)(b * Cv + c0 + g) * Lv))[j] = o;
    }
}

// ---------------------------------------------------------------------------
extern "C" void kernel_launch(void* const* d_in, const int* in_sizes, int n_in,
                              void* d_out, int out_size) {
    const float* x  = (const float*)d_in[0];   // (B, C, L) f32
    const float* dt = (const float*)d_in[1];   // (B, L)    f32
    const float* kt = (const float*)d_in[2];   // (1, 1, K) f32
    float* out = (float*)d_out;                // (B, C, L) f32

    cudaFuncSetAttribute(fused_kernel,
                         cudaFuncAttributeMaxDynamicSharedMemorySize, SMEM_BYTES);

    fused_kernel<<<Bv * Cv / Gv, TPB, SMEM_BYTES>>>(x, dt, kt, out);
}

// round 9
// speedup vs baseline: 1.3064x; 1.3064x over previous
#include <cuda_runtime.h>
#include <cuda_bf16.h>

// Problem shape (fixed by the dataset)
#define Bv 8
#define Cv 256
#define Lv 4096
#define Kv 8
#define Gv 2              // channels per CTA (share weight computation)
#define TPB 256
#define NJ (Lv / 4)       // float4s per row = 1024
#define ITERS (NJ / TPB)  // 4

#define SMEM_BYTES (2 * Gv * Lv * 4)

// ---------------------------------------------------------------------------
// Math:
//  softmax identity  w_k(l) = E[l-k] / sum_k' E[l-k'],  E = exp(dt)
//  (the exp(-dt[l]) base cancels -> 12 exps per 4 elements).
//  windowed numerators: num_c = sum_{m=c+1}^{c+8} E[m]*x[m] -> the 4 elements
//  of a float4 share the products p[m] = E[m]*x[m]: 11 MUL + 14 ADD replaces
//  32 FMA. at[l] = num*rcp(den);  at[l<7] = 0 exactly (BIG sentinel).
// ---------------------------------------------------------------------------
template<bool FIRST>
__device__ __forceinline__ void pass1_iter(
    const int j,
    const float4* __restrict__ dtr,
    const float4* __restrict__ xr0,
    const float4* __restrict__ xr1,
    const float*  __restrict__ ktr,     // [Kv] in registers
    float4* __restrict__ sat,           // [Gv*NJ]
    float4* __restrict__ sap,           // [Gv*NJ]
    float*  __restrict__ gr)            // [Gv*3] Gram accumulators
{
    const float4 zero4 = make_float4(0.f, 0.f, 0.f, 0.f);

    // dt window [4j-8 .. 4j+3] -> E = exp(dt)
    float4 dm2 = FIRST ? ((j >= 2) ? dtr[j - 2] : zero4) : dtr[j - 2];
    float4 dm1 = FIRST ? ((j >= 1) ? dtr[j - 1] : zero4) : dtr[j - 1];
    float4 dd0 = dtr[j];
    float Ew[12] = {dm2.x, dm2.y, dm2.z, dm2.w,
                    dm1.x, dm1.y, dm1.z, dm1.w,
                    dd0.x, dd0.y, dd0.z, dd0.w};
#pragma unroll
    for (int m = 0; m < 12; m++) Ew[m] = __expf(Ew[m]);

    // reciprocal 8-tap sums (shared factored partials)
    float inv[4];
    {
        float c45  = Ew[4] + Ew[5];
        float c67  = Ew[6] + Ew[7];
        float core = (c45 + c67) + Ew[8];          // E[4..8]
        float s23  = Ew[2] + Ew[3];
        float s910 = Ew[9] + Ew[10];
        inv[0] = __fdividef(1.0f, core + (Ew[1] + s23));    // E[1..8]
        inv[1] = __fdividef(1.0f, core + (s23 + Ew[9]));    // E[2..9]
        inv[2] = __fdividef(1.0f, core + (Ew[3] + s910));   // E[3..10]
        inv[3] = __fdividef(1.0f, core + (s910 + Ew[11]));  // E[4..11]
    }

#pragma unroll
    for (int g = 0; g < Gv; g++) {
        const float4* xr = (g == 0) ? xr0 : xr1;
        float4 xm2 = FIRST ? ((j >= 2) ? xr[j - 2] : zero4) : xr[j - 2];
        float4 xm1 = FIRST ? ((j >= 1) ? xr[j - 1] : zero4) : xr[j - 1];
        float4 x0  = xr[j];
        float xw[12] = {xm2.x, xm2.y, xm2.z, xm2.w,
                        xm1.x, xm1.y, xm1.z, xm1.w,
                        x0.x,  x0.y,  x0.z,  x0.w};

        // products p[m] = E[m]*x[m], m = 1..11; windowed numerators
        float num[4];
        {
            float p1 = Ew[1] * xw[1],  p2 = Ew[2] * xw[2],  p3 = Ew[3] * xw[3];
            float p4 = Ew[4] * xw[4],  p5 = Ew[5] * xw[5],  p6 = Ew[6] * xw[6];
            float p7 = Ew[7] * xw[7],  p8 = Ew[8] * xw[8],  p9 = Ew[9] * xw[9];
            float p10 = Ew[10] * xw[10], p11 = Ew[11] * xw[11];
            float c45  = p4 + p5;
            float c67  = p6 + p7;
            float core = (c45 + c67) + p8;         // p[4..8]
            float s23  = p2 + p3;
            float s910 = p9 + p10;
            num[0] = core + (p1 + s23);            // p[1..8]
            num[1] = core + (s23 + p9);            // p[2..9]
            num[2] = core + (p3 + s910);           // p[3..10]
            num[3] = core + (s910 + p11);          // p[4..11]
        }

        float4 atv, apv;
        float* atf = (float*)&atv;
        float* apf = (float*)&apv;
#pragma unroll
        for (int c = 0; c < 4; c++) {
            float a_p = 0.f;
#pragma unroll
            for (int k = 0; k < Kv; k++)
                a_p = fmaf(ktr[k], xw[8 + c - k], a_p);
            float a_t = num[c] * inv[c];
            if (FIRST) {
                if (4 * j + c < Kv - 1) a_t = 0.f;   // BIG-sentinel mask
            }
            atf[c] = a_t;
            apf[c] = a_p;
            gr[g * 3 + 0] = fmaf(a_t, a_t, gr[g * 3 + 0]);
            gr[g * 3 + 1] = fmaf(a_t, a_p, gr[g * 3 + 1]);
            gr[g * 3 + 2] = fmaf(a_p, a_p, gr[g * 3 + 2]);
        }
        sat[g * NJ + j] = atv;
        sap[g * NJ + j] = apv;
    }
}

__global__ void __launch_bounds__(TPB, 3) fused_kernel(
    const float* __restrict__ x,
    const float* __restrict__ dt,
    const float* __restrict__ kt,
    float* __restrict__ out)
{
    extern __shared__ float smem[];
    float4* sat = (float4*)smem;               // [Gv][NJ]
    float4* sap = (float4*)(smem + Gv * Lv);   // [Gv][NJ]
    __shared__ float sred[8][Gv * 3];
    __shared__ float scoef[Gv][2];

    const int b   = blockIdx.x >> 7;           // / (Cv/Gv = 128)
    const int c0  = (blockIdx.x & 127) * Gv;
    const int tid = threadIdx.x;
    const int lid = tid & 31;
    const int wid = tid >> 5;

    const float4* dtr = (const float4*)(dt + (size_t)b * Lv);
    const float4* xr0 = (const float4*)(x + (size_t)(b * Cv + c0 + 0) * Lv);
    const float4* xr1 = (const float4*)(x + (size_t)(b * Cv + c0 + 1) * Lv);

    float ktr[Kv];
#pragma unroll
    for (int k = 0; k < Kv; k++) ktr[k] = __ldg(&kt[k]);

    float gr[Gv * 3];
#pragma unroll
    for (int q = 0; q < Gv * 3; q++) gr[q] = 0.f;

    // Iteration 0 (peeled: halo zero-fill + l<7 mask live only here)
    pass1_iter<true>(tid, dtr, xr0, xr1, ktr, sat, sap, gr);
    // Iterations 1..3 (guard-free)
#pragma unroll 1
    for (int i = 1; i < ITERS; i++)
        pass1_iter<false>(tid + i * TPB, dtr, xr0, xr1, ktr, sat, sap, gr);

    // ---- block reduction of 6 Gram scalars ----
#pragma unroll
    for (int q = 0; q < Gv * 3; q++) {
        float v = gr[q];
#pragma unroll
        for (int o = 16; o > 0; o >>= 1)
            v += __shfl_xor_sync(0xffffffffu, v, o);
        if (lid == 0) sred[wid][q] = v;
    }
    __syncthreads();
    if (tid < Gv) {
        float G00 = 0.f, G01 = 0.f, G11 = 0.f;
#pragma unroll
        for (int wq = 0; wq < 8; wq++) {
            G00 += sred[wq][tid * 3 + 0];
            G01 += sred[wq][tid * 3 + 1];
            G11 += sred[wq][tid * 3 + 2];
        }
        // scores row0 = softmax([G00,G01]); row1 = softmax([G01,G11])
        // out = 0.5*((s00+s10)*at + ((1-s00)+(1-s10))*ap)
        float s00 = 1.0f / (1.0f + __expf(G01 - G00));
        float s10 = 1.0f / (1.0f + __expf(G11 - G01));
        scoef[tid][0] = 0.5f * (s00 + s10);
        scoef[tid][1] = 0.5f * ((1.0f - s00) + (1.0f - s10));
    }
    __syncthreads();

    // ---- pass 2: out = ca*at + cb*ap (LDS.128 -> STG.128) ----
#pragma unroll
    for (int g = 0; g < Gv; g++) {
        const float ca = scoef[g][0];
        const float cb = scoef[g][1];
        float4* orow = (float4*)(out + (size_t)(b * Cv + c0 + g) * Lv);
#pragma unroll
        for (int i = 0; i < ITERS; i++) {
            const int j = tid + i * TPB;
            float4 a = sat[g * NJ + j];
            float4 p = sap[g * NJ + j];
            float4 o;
            o.x = fmaf(ca, a.x, cb * p.x);
            o.y = fmaf(ca, a.y, cb * p.y);
            o.z = fmaf(ca, a.z, cb * p.z);
            o.w = fmaf(ca, a.w, cb * p.w);
            orow[j] = o;
        }
    }
}

// ---------------------------------------------------------------------------
extern "C" void kernel_launch(void* const* d_in, const int* in_sizes, int n_in,
                              void* d_out, int out_size) {
    const float* x  = (const float*)d_in[0];   // (B, C, L) f32
    const float* dt = (const float*)d_in[1];   // (B, L)    f32
    const float* kt = (const float*)d_in[2];   // (1, 1, K) f32
    float* out = (float*)d_out;                // (B, C, L) f32

    cudaFuncSetAttribute(fused_kernel,
                         cudaFuncAttributeMaxDynamicSharedMemorySize, SMEM_BYTES);

    fused_kernel<<<Bv * Cv / Gv, TPB, SMEM_BYTES>>>(x, dt, kt, out);
}